// round 13
// baseline (speedup 1.0000x reference)
#include <cuda_runtime.h>
#include <cuda_bf16.h>
#include <cstdint>

#define KMIX 10
#define TILE_PIX 64           // pixels per CTA
#define THREADS 64

// static smem tile: pi/mu/ls 2560 B each, u/eps 256 B each, + mbarrier
__global__ void __launch_bounds__(THREADS) melnet_gmm_final_kernel(
    const float* __restrict__ mu,
    const float* __restrict__ log_std,
    const float* __restrict__ pi_logits,
    const float* __restrict__ u_cat,
    const float* __restrict__ eps,
    float* __restrict__ out,
    int n)
{
    __shared__ __align__(16) float s_pi[TILE_PIX * KMIX];
    __shared__ __align__(16) float s_mu[TILE_PIX * KMIX];
    __shared__ __align__(16) float s_ls[TILE_PIX * KMIX];
    __shared__ __align__(16) float s_u [TILE_PIX];
    __shared__ __align__(16) float s_e [TILE_PIX];
    __shared__ __align__(8)  unsigned long long s_mbar;

    const int tid  = threadIdx.x;
    const long base = (long)blockIdx.x * TILE_PIX;

    uint32_t mbar;
    {
        uint64_t tmp;
        asm("cvta.to.shared.u64 %0, %1;" : "=l"(tmp) : "l"((void*)&s_mbar));
        mbar = (uint32_t)tmp;
    }

    // tid0: init -> fence -> issue immediately (self-ordered); others sync then wait
    if (tid == 0) {
        asm volatile("mbarrier.init.shared.b64 [%0], 1;" :: "r"(mbar) : "memory");
        asm volatile("fence.proxy.async.shared::cta;" ::: "memory");

        const uint32_t row_bytes = TILE_PIX * KMIX * 4;   // 2560
        const uint32_t vec_bytes = TILE_PIX * 4;          // 256
        const uint32_t total_tx  = 3 * row_bytes + 2 * vec_bytes;
        asm volatile("mbarrier.arrive.expect_tx.shared.b64 _, [%0], %1;"
                     :: "r"(mbar), "r"(total_tx) : "memory");

        uint32_t d_pi, d_mu, d_ls, d_u, d_e;
        { uint64_t t; asm("cvta.to.shared.u64 %0, %1;" : "=l"(t) : "l"((void*)s_pi)); d_pi = (uint32_t)t; }
        { uint64_t t; asm("cvta.to.shared.u64 %0, %1;" : "=l"(t) : "l"((void*)s_mu)); d_mu = (uint32_t)t; }
        { uint64_t t; asm("cvta.to.shared.u64 %0, %1;" : "=l"(t) : "l"((void*)s_ls)); d_ls = (uint32_t)t; }
        { uint64_t t; asm("cvta.to.shared.u64 %0, %1;" : "=l"(t) : "l"((void*)s_u )); d_u  = (uint32_t)t; }
        { uint64_t t; asm("cvta.to.shared.u64 %0, %1;" : "=l"(t) : "l"((void*)s_e )); d_e  = (uint32_t)t; }

#define BULK_CP(dst, src, nbytes)                                               \
        asm volatile("cp.async.bulk.shared::cta.global.mbarrier::complete_tx::bytes " \
                     "[%0], [%1], %2, [%3];"                                    \
                     :: "r"(dst), "l"(src), "r"(nbytes), "r"(mbar) : "memory")

        BULK_CP(d_pi, pi_logits + base * KMIX, row_bytes);
        BULK_CP(d_mu, mu        + base * KMIX, row_bytes);
        BULK_CP(d_ls, log_std   + base * KMIX, row_bytes);
        BULK_CP(d_u,  u_cat     + base,        vec_bytes);
        BULK_CP(d_e,  eps       + base,        vec_bytes);
#undef BULK_CP
    }
    __syncthreads();   // init (and issue) visible to all before waiting

    // wait for the tile (acquire ordering for subsequent LDS)
    {
        uint32_t done;
        asm volatile(
            "{\n\t.reg .pred p;\n\t"
            "mbarrier.try_wait.parity.acquire.cta.shared::cta.b64 p, [%1], 0;\n\t"
            "selp.b32 %0, 1, 0, p;\n\t}"
            : "=r"(done) : "r"(mbar) : "memory");
        while (!done) {
            asm volatile(
                "{\n\t.reg .pred p;\n\t"
                "mbarrier.try_wait.parity.acquire.cta.shared::cta.b64 p, [%1], 0, 0x989680;\n\t"
                "selp.b32 %0, 1, 0, p;\n\t}"
                : "=r"(done) : "r"(mbar) : "memory");
        }
    }

    // ---- compute pixel `tid` entirely from smem ----
    const float2* sp = reinterpret_cast<const float2*>(s_pi) + tid * 5;
    float2 q0 = sp[0], q1 = sp[1], q2 = sp[2], q3 = sp[3], q4 = sp[4];
    float u = s_u[tid];

    float l[KMIX] = { q0.x, q0.y, q1.x, q1.y, q2.x,
                      q2.y, q3.x, q3.y, q4.x, q4.y };

    // softmax + inverse-CDF pick, arithmetic byte-identical to the reference
    float m = l[0];
#pragma unroll
    for (int j = 1; j < KMIX; j++) m = fmaxf(m, l[j]);

    float e[KMIX];
    float S = 0.0f;
#pragma unroll
    for (int j = 0; j < KMIX; j++) {
        e[j] = expf(__fadd_rn(l[j], -m));
        S = __fadd_rn(S, e[j]);
    }

    float cdf = 0.0f;
    int k = 0;
#pragma unroll
    for (int j = 0; j < KMIX; j++) {
        float pj = __fdiv_rn(e[j], S);     // exact IEEE division, matching reference
        cdf = __fadd_rn(cdf, pj);
        k += (cdf < u) ? 1 : 0;
    }
    if (k > KMIX - 1) k = KMIX - 1;

    float mu_k = s_mu[tid * KMIX + k];     // bit-identical to a global gather
    float ls_k = s_ls[tid * KMIX + k];
    float ep   = s_e[tid];

    long p = base + tid;
    if (p < n)
        __stcs(out + p, __fadd_rn(mu_k, __fmul_rn(expf(ls_k), ep)));
}

extern "C" void kernel_launch(void* const* d_in, const int* in_sizes, int n_in,
                              void* d_out, int out_size)
{
    // metadata order: mu, log_std, pi_logits, u_cat, eps
    const float* mu        = (const float*)d_in[0];
    const float* log_std   = (const float*)d_in[1];
    const float* pi_logits = (const float*)d_in[2];
    const float* u_cat     = (const float*)d_in[3];
    const float* eps       = (const float*)d_in[4];
    float* out = (float*)d_out;

    int n = in_sizes[3];                         // 4,194,304 — divisible by TILE_PIX
    int tiles = (n + TILE_PIX - 1) / TILE_PIX;   // 65536

    melnet_gmm_final_kernel<<<tiles, THREADS>>>(mu, log_std, pi_logits,
                                                u_cat, eps, out, n);
}

// round 14
// speedup vs baseline: 1.0043x; 1.0043x over previous
#include <cuda_runtime.h>
#include <cuda_bf16.h>
#include <cstdint>

#define KMIX 10
#define TILE_PIX 32           // pixels per CTA (single warp)
#define THREADS 32

// static smem tile: pi/mu/ls 1280 B each, u/eps 128 B each, + mbarrier
__global__ void __launch_bounds__(THREADS) melnet_gmm_bulk32_kernel(
    const float* __restrict__ mu,
    const float* __restrict__ log_std,
    const float* __restrict__ pi_logits,
    const float* __restrict__ u_cat,
    const float* __restrict__ eps,
    float* __restrict__ out,
    int n)
{
    __shared__ __align__(16) float s_pi[TILE_PIX * KMIX];
    __shared__ __align__(16) float s_mu[TILE_PIX * KMIX];
    __shared__ __align__(16) float s_ls[TILE_PIX * KMIX];
    __shared__ __align__(16) float s_u [TILE_PIX];
    __shared__ __align__(16) float s_e [TILE_PIX];
    __shared__ __align__(8)  unsigned long long s_mbar;

    const int tid  = threadIdx.x;
    const long base = (long)blockIdx.x * TILE_PIX;

    uint32_t mbar;
    {
        uint64_t tmp;
        asm("cvta.to.shared.u64 %0, %1;" : "=l"(tmp) : "l"((void*)&s_mbar));
        mbar = (uint32_t)tmp;
    }

    // lane0 of the single warp: init -> fence -> issue (self-ordered)
    if (tid == 0) {
        asm volatile("mbarrier.init.shared.b64 [%0], 1;" :: "r"(mbar) : "memory");
        asm volatile("fence.proxy.async.shared::cta;" ::: "memory");

        const uint32_t row_bytes = TILE_PIX * KMIX * 4;   // 1280
        const uint32_t vec_bytes = TILE_PIX * 4;          // 128
        const uint32_t total_tx  = 3 * row_bytes + 2 * vec_bytes;
        asm volatile("mbarrier.arrive.expect_tx.shared.b64 _, [%0], %1;"
                     :: "r"(mbar), "r"(total_tx) : "memory");

        uint32_t d_pi, d_mu, d_ls, d_u, d_e;
        { uint64_t t; asm("cvta.to.shared.u64 %0, %1;" : "=l"(t) : "l"((void*)s_pi)); d_pi = (uint32_t)t; }
        { uint64_t t; asm("cvta.to.shared.u64 %0, %1;" : "=l"(t) : "l"((void*)s_mu)); d_mu = (uint32_t)t; }
        { uint64_t t; asm("cvta.to.shared.u64 %0, %1;" : "=l"(t) : "l"((void*)s_ls)); d_ls = (uint32_t)t; }
        { uint64_t t; asm("cvta.to.shared.u64 %0, %1;" : "=l"(t) : "l"((void*)s_u )); d_u  = (uint32_t)t; }
        { uint64_t t; asm("cvta.to.shared.u64 %0, %1;" : "=l"(t) : "l"((void*)s_e )); d_e  = (uint32_t)t; }

#define BULK_CP(dst, src, nbytes)                                               \
        asm volatile("cp.async.bulk.shared::cta.global.mbarrier::complete_tx::bytes " \
                     "[%0], [%1], %2, [%3];"                                    \
                     :: "r"(dst), "l"(src), "r"(nbytes), "r"(mbar) : "memory")

        BULK_CP(d_pi, pi_logits + base * KMIX, row_bytes);
        BULK_CP(d_mu, mu        + base * KMIX, row_bytes);
        BULK_CP(d_ls, log_std   + base * KMIX, row_bytes);
        BULK_CP(d_u,  u_cat     + base,        vec_bytes);
        BULK_CP(d_e,  eps       + base,        vec_bytes);
#undef BULK_CP
    }
    __syncwarp();      // single-warp CTA: warp sync suffices for init visibility

    // wait for the tile (acquire ordering for subsequent LDS)
    {
        uint32_t done;
        asm volatile(
            "{\n\t.reg .pred p;\n\t"
            "mbarrier.try_wait.parity.acquire.cta.shared::cta.b64 p, [%1], 0;\n\t"
            "selp.b32 %0, 1, 0, p;\n\t}"
            : "=r"(done) : "r"(mbar) : "memory");
        while (!done) {
            asm volatile(
                "{\n\t.reg .pred p;\n\t"
                "mbarrier.try_wait.parity.acquire.cta.shared::cta.b64 p, [%1], 0, 0x989680;\n\t"
                "selp.b32 %0, 1, 0, p;\n\t}"
                : "=r"(done) : "r"(mbar) : "memory");
        }
    }

    // ---- compute pixel `tid` entirely from smem ----
    const float2* sp = reinterpret_cast<const float2*>(s_pi) + tid * 5;
    float2 q0 = sp[0], q1 = sp[1], q2 = sp[2], q3 = sp[3], q4 = sp[4];
    float u = s_u[tid];

    float l[KMIX] = { q0.x, q0.y, q1.x, q1.y, q2.x,
                      q2.y, q3.x, q3.y, q4.x, q4.y };

    // softmax + inverse-CDF pick, arithmetic byte-identical to the reference
    float m = l[0];
#pragma unroll
    for (int j = 1; j < KMIX; j++) m = fmaxf(m, l[j]);

    float e[KMIX];
    float S = 0.0f;
#pragma unroll
    for (int j = 0; j < KMIX; j++) {
        e[j] = expf(__fadd_rn(l[j], -m));
        S = __fadd_rn(S, e[j]);
    }

    float cdf = 0.0f;
    int k = 0;
#pragma unroll
    for (int j = 0; j < KMIX; j++) {
        float pj = __fdiv_rn(e[j], S);     // exact IEEE division, matching reference
        cdf = __fadd_rn(cdf, pj);
        k += (cdf < u) ? 1 : 0;
    }
    if (k > KMIX - 1) k = KMIX - 1;

    float mu_k = s_mu[tid * KMIX + k];     // bit-identical to a global gather
    float ls_k = s_ls[tid * KMIX + k];
    float ep   = s_e[tid];

    long p = base + tid;
    if (p < n)
        out[p] = __fadd_rn(mu_k, __fmul_rn(expf(ls_k), ep));
}

extern "C" void kernel_launch(void* const* d_in, const int* in_sizes, int n_in,
                              void* d_out, int out_size)
{
    // metadata order: mu, log_std, pi_logits, u_cat, eps
    const float* mu        = (const float*)d_in[0];
    const float* log_std   = (const float*)d_in[1];
    const float* pi_logits = (const float*)d_in[2];
    const float* u_cat     = (const float*)d_in[3];
    const float* eps       = (const float*)d_in[4];
    float* out = (float*)d_out;

    int n = in_sizes[3];                         // 4,194,304 — divisible by TILE_PIX
    int tiles = (n + TILE_PIX - 1) / TILE_PIX;   // 131072

    melnet_gmm_bulk32_kernel<<<tiles, THREADS>>>(mu, log_std, pi_logits,
                                                 u_cat, eps, out, n);
}